// round 4
// baseline (speedup 1.0000x reference)
#include <cuda_runtime.h>
#include <cuda_bf16.h>
#include <cuda_fp8.h>
#include <cstdint>
#include <cstddef>

// ---------------- problem constants ----------------
#define B_ROWS 4096
#define C_ROWS 65536
#define DIM    1024
#define TOPK   5

// ---------------- GEMM tiling (fp8 mma.sync) ----------------
#define BM 128
#define BN 256
#define BK 128                  // fp8 elements per stage (128 B rows -> SW128)
#define NS 3                    // cp.async stages
#define NKI (DIM / BK)          // 8
#define NTILES (C_ROWS / BN)    // 256
#define CAND_PER_TILE 8
#define CAND_PER_ROW (NTILES * CAND_PER_TILE)  // 2048
#define RESCORE 32

#define A_BYTES (BM * BK)                  // 16384
#define B_BYTES (BN * BK)                  // 32768
#define STAGE_BYTES (A_BYTES + B_BYTES)    // 49152
#define CS_STRIDE 260
#define SMEM_BYTES (NS * STAGE_BYTES)      // 147456 (>= 128*260*4 = 133120 epilogue)

// SW128 swizzle (Swizzle<3,4,3>)
#define SWZ(o) ((o) ^ (((o) >> 3) & 0x70))

// ---------------- device scratch ----------------
__device__ __align__(16) uint8_t g_memf8[(size_t)C_ROWS * DIM]; // normalized*64 -> e4m3
__device__ __align__(16) uint8_t g_xf8[(size_t)B_ROWS * DIM];   // normalized*64 -> e4m3
__device__ float g_minv[C_ROWS];
__device__ float g_xinv[B_ROWS];
__device__ __align__(16) float g_cv[(size_t)B_ROWS * CAND_PER_ROW];
__device__ __align__(16) int   g_ci[(size_t)B_ROWS * CAND_PER_ROW];

// ---------------- PTX helpers ----------------
__device__ __forceinline__ void cp16(uint32_t saddr, const void* gaddr) {
    asm volatile("cp.async.cg.shared.global [%0], [%1], 16;" :: "r"(saddr), "l"(gaddr));
}
__device__ __forceinline__ void cp_commit() {
    asm volatile("cp.async.commit_group;" ::: "memory");
}
__device__ __forceinline__ void ldsm4(uint32_t (&r)[4], uint32_t addr) {
    asm volatile("ldmatrix.sync.aligned.m8n8.x4.shared.b16 {%0,%1,%2,%3}, [%4];"
                 : "=r"(r[0]), "=r"(r[1]), "=r"(r[2]), "=r"(r[3]) : "r"(addr));
}
// fp8 e4m3 MMA: D[16x8] += A[16x32] * B[32x8]
__device__ __forceinline__ void mma_fp8(float (&c)[4], const uint32_t (&a)[4],
                                        uint32_t b0, uint32_t b1) {
    asm volatile(
        "mma.sync.aligned.m16n8k32.row.col.f32.e4m3.e4m3.f32 "
        "{%0,%1,%2,%3},{%4,%5,%6,%7},{%8,%9},{%0,%1,%2,%3};"
        : "+f"(c[0]), "+f"(c[1]), "+f"(c[2]), "+f"(c[3])
        : "r"(a[0]), "r"(a[1]), "r"(a[2]), "r"(a[3]), "r"(b0), "r"(b1));
}

// ---------------- prep: normalize + fp8 conversion (scale 64) ----------------
__device__ __forceinline__ void prep_row_fp8(const float* __restrict__ src,
                                             uint8_t* __restrict__ dst,
                                             float* __restrict__ inv) {
    int row = blockIdx.x;
    const float4* s4 = reinterpret_cast<const float4*>(src + (size_t)row * DIM);
    float4 v = s4[threadIdx.x];
    float ss = v.x * v.x + v.y * v.y + v.z * v.z + v.w * v.w;
    #pragma unroll
    for (int o = 16; o; o >>= 1) ss += __shfl_down_sync(0xffffffffu, ss, o);
    __shared__ float warpsum[8];
    __shared__ float s_inv;
    if ((threadIdx.x & 31) == 0) warpsum[threadIdx.x >> 5] = ss;
    __syncthreads();
    if (threadIdx.x == 0) {
        float t = 0.f;
        #pragma unroll
        for (int i = 0; i < 8; i++) t += warpsum[i];
        float iv = 1.0f / fmaxf(sqrtf(t), 1e-12f);
        inv[row] = iv;
        s_inv = iv;
    }
    __syncthreads();
    float sc = s_inv * 64.0f;   // common positive scale: ranking-invariant
    __nv_fp8x2_storage_t p0 = __nv_cvt_float2_to_fp8x2(
        make_float2(v.x * sc, v.y * sc), __NV_SATFINITE, __NV_E4M3);
    __nv_fp8x2_storage_t p1 = __nv_cvt_float2_to_fp8x2(
        make_float2(v.z * sc, v.w * sc), __NV_SATFINITE, __NV_E4M3);
    uint32_t w = (uint32_t)p0 | ((uint32_t)p1 << 16);
    reinterpret_cast<uint32_t*>(dst)[(size_t)row * (DIM / 4) + threadIdx.x] = w;
}
__global__ void prep_mem_kernel(const float* __restrict__ src) {
    prep_row_fp8(src, g_memf8, g_minv);
}
__global__ void prep_x_kernel(const float* __restrict__ src) {
    prep_row_fp8(src, g_xf8, g_xinv);
}

// ---------------- coarse fp8 GEMM + per-tile top-8 ----------------
__device__ __forceinline__ void fill_stage(uint32_t su, int bm, int bn, int buf,
                                           int kc, int tid) {
    uint32_t base = su + buf * STAGE_BYTES;
    const uint8_t* gA = g_xf8   + (size_t)(bm * BM) * DIM + kc * BK;
    const uint8_t* gB = g_memf8 + (size_t)(bn * BN) * DIM + kc * BK;
    // A: 128 rows x 8 chunks(16B) = 1024 chunks, 4 per thread
    #pragma unroll
    for (int i = 0; i < 4; i++) {
        int c = i * 256 + tid;
        int row = c >> 3, off = c & 7;
        uint32_t bo = (uint32_t)(row * BK + off * 16);
        cp16(base + SWZ(bo), gA + (size_t)row * DIM + off * 16);
    }
    // B: 256 rows x 8 chunks = 2048 chunks, 8 per thread
    #pragma unroll
    for (int i = 0; i < 8; i++) {
        int c = i * 256 + tid;
        int row = c >> 3, off = c & 7;
        uint32_t bo = (uint32_t)(row * BK + off * 16);
        cp16(base + A_BYTES + SWZ(bo), gB + (size_t)row * DIM + off * 16);
    }
    cp_commit();
}

__global__ __launch_bounds__(256, 1) void gemm_topk_kernel() {
    extern __shared__ __align__(1024) char smem[];
    const uint32_t su = (uint32_t)__cvta_generic_to_shared(smem);
    const int tid = threadIdx.x;
    const int bm = blockIdx.x;   // fast dim: CTAs sharing the B tile run together
    const int bn = blockIdx.y;

    const int lane = tid & 31;
    const int w = tid >> 5;
    const int wm = (w & 1) * 64;   // 2 warps on M
    const int wn = (w >> 1) * 64;  // 4 warps on N

    float acc[4][8][4];
    #pragma unroll
    for (int i = 0; i < 4; i++)
        #pragma unroll
        for (int j = 0; j < 8; j++)
            #pragma unroll
            for (int q = 0; q < 4; q++) acc[i][j][q] = 0.f;

    // prologue: stages 0,1
    fill_stage(su, bm, bn, 0, 0, tid);
    fill_stage(su, bm, bn, 1, 1, tid);

    // precomputed ldsm base offsets (within a stage)
    const uint32_t a_row = (uint32_t)(wm + (lane & 15));
    const uint32_t a_koff = (uint32_t)((lane >> 4) * 16);
    const int mat = lane >> 3;
    const uint32_t b_row = (uint32_t)(wn + ((mat >> 1) << 3) + (lane & 7));
    const uint32_t b_koff = (uint32_t)((mat & 1) * 16);

    for (int it = 0; it < NKI; ++it) {
        if (it + 2 < NKI) fill_stage(su, bm, bn, (it + 2) % NS, it + 2, tid);
        else cp_commit();  // empty group keeps wait_group arithmetic valid
        asm volatile("cp.async.wait_group 1;" ::: "memory");
        __syncthreads();

        uint32_t abase = su + (it % NS) * STAGE_BYTES;
        uint32_t bbase = abase + A_BYTES;
        #pragma unroll
        for (int kk = 0; kk < 4; ++kk) {
            uint32_t a[4][4];
            #pragma unroll
            for (int mi = 0; mi < 4; ++mi) {
                uint32_t bo = (a_row + mi * 16) * BK + kk * 32 + a_koff;
                ldsm4(a[mi], abase + SWZ(bo));
            }
            uint32_t bf[8][2];
            #pragma unroll
            for (int bp = 0; bp < 4; ++bp) {
                uint32_t bo = (b_row + bp * 16) * BK + kk * 32 + b_koff;
                uint32_t r[4];
                ldsm4(r, bbase + SWZ(bo));
                bf[bp * 2 + 0][0] = r[0]; bf[bp * 2 + 0][1] = r[1];
                bf[bp * 2 + 1][0] = r[2]; bf[bp * 2 + 1][1] = r[3];
            }
            #pragma unroll
            for (int mi = 0; mi < 4; ++mi)
                #pragma unroll
                for (int ni = 0; ni < 8; ++ni)
                    mma_fp8(acc[mi][ni], a[mi], bf[ni][0], bf[ni][1]);
        }
        __syncthreads();
    }

    // epilogue: dump sims to smem, per-row top-8 over BN=256
    float* Cs = reinterpret_cast<float*>(smem);
    #pragma unroll
    for (int mi = 0; mi < 4; ++mi) {
        #pragma unroll
        for (int ni = 0; ni < 8; ++ni) {
            int rb = wm + mi * 16 + (lane >> 2);
            int cb = wn + ni * 8 + (lane & 3) * 2;
            Cs[rb * CS_STRIDE + cb]           = acc[mi][ni][0];
            Cs[rb * CS_STRIDE + cb + 1]       = acc[mi][ni][1];
            Cs[(rb + 8) * CS_STRIDE + cb]     = acc[mi][ni][2];
            Cs[(rb + 8) * CS_STRIDE + cb + 1] = acc[mi][ni][3];
        }
    }
    __syncthreads();

    if (tid < BM) {
        const float* rowp = Cs + tid * CS_STRIDE;
        float tv[CAND_PER_TILE];
        int   tc[CAND_PER_TILE];
        #pragma unroll
        for (int i = 0; i < CAND_PER_TILE; i++) { tv[i] = -1e30f; tc[i] = 0; }
        for (int c = 0; c < BN; ++c) {
            float v = rowp[c];
            if (v > tv[CAND_PER_TILE - 1]) {
                int p = CAND_PER_TILE - 1;
                while (p > 0 && v > tv[p - 1]) { tv[p] = tv[p - 1]; tc[p] = tc[p - 1]; --p; }
                tv[p] = v; tc[p] = c;
            }
        }
        size_t base = ((size_t)(bm * BM + tid) * NTILES + bn) * CAND_PER_TILE;
        #pragma unroll
        for (int i = 0; i < CAND_PER_TILE; i++) {
            g_cv[base + i] = tv[i];
            g_ci[base + i] = bn * BN + tc[i];
        }
    }
}

// ---------------- phase 2: exact rescore, top-5, softmax, weighted gather ----------------
__global__ __launch_bounds__(256) void rescore_out_kernel(const float* __restrict__ x,
                                                          const float* __restrict__ mem,
                                                          float* __restrict__ out) {
    const int row = blockIdx.x;
    const int tid = threadIdx.x, lane = tid & 31, warp = tid >> 5;
    __shared__ float sv[CAND_PER_ROW];
    __shared__ float wv[8];
    __shared__ int   wp[8];
    __shared__ int   cpos[RESCORE];
    __shared__ float ev[RESCORE];
    __shared__ int   em[RESCORE];
    __shared__ float wgt[TOPK];
    __shared__ int   sidx[TOPK];

    const float4* cv4 = reinterpret_cast<const float4*>(g_cv + (size_t)row * CAND_PER_ROW);
    float4* sv4 = reinterpret_cast<float4*>(sv);
    for (int j = tid; j < CAND_PER_ROW / 4; j += 256) sv4[j] = cv4[j];
    __syncthreads();

    // approx top-32 by coarse score (iterative extract-max)
    for (int i = 0; i < RESCORE; ++i) {
        float best = -1e30f; int bp = -1;
        for (int j = tid; j < CAND_PER_ROW; j += 256) {
            float v = sv[j];
            if (v > best) { best = v; bp = j; }
        }
        #pragma unroll
        for (int o = 16; o; o >>= 1) {
            float ov = __shfl_down_sync(0xffffffffu, best, o);
            int   op = __shfl_down_sync(0xffffffffu, bp, o);
            if (ov > best) { best = ov; bp = op; }
        }
        if (lane == 0) { wv[warp] = best; wp[warp] = bp; }
        __syncthreads();
        if (tid == 0) {
            float bb = wv[0]; int pp = wp[0];
            #pragma unroll
            for (int w2 = 1; w2 < 8; w2++) if (wv[w2] > bb) { bb = wv[w2]; pp = wp[w2]; }
            cpos[i] = pp;
            sv[pp] = -1e30f;
        }
        __syncthreads();
    }

    // exact fp32 rescore of 32 candidates (4 per warp)
    const float4* xr = reinterpret_cast<const float4*>(x + (size_t)row * DIM);
    for (int i = warp; i < RESCORE; i += 8) {
        int mi = g_ci[(size_t)row * CAND_PER_ROW + cpos[i]];
        const float4* mr = reinterpret_cast<const float4*>(mem + (size_t)mi * DIM);
        float s = 0.f;
        for (int j = lane; j < DIM / 4; j += 32) {
            float4 a = xr[j], b = mr[j];
            s += a.x * b.x + a.y * b.y + a.z * b.z + a.w * b.w;
        }
        #pragma unroll
        for (int o = 16; o; o >>= 1) s += __shfl_down_sync(0xffffffffu, s, o);
        if (lane == 0) { ev[i] = s * g_minv[mi] * g_xinv[row]; em[i] = mi; }
    }
    __syncthreads();

    if (tid == 0) {
        bool used[RESCORE];
        #pragma unroll
        for (int i = 0; i < RESCORE; i++) used[i] = false;
        float tv[TOPK]; int ti[TOPK];
        #pragma unroll
        for (int r = 0; r < TOPK; ++r) {
            float bb = -1e30f; int pp = 0;
            for (int i = 0; i < RESCORE; i++)
                if (!used[i] && ev[i] > bb) { bb = ev[i]; pp = i; }
            used[pp] = true; tv[r] = bb; ti[r] = pp;
        }
        float mx = tv[0];
        float e[TOPK], se = 0.f;
        #pragma unroll
        for (int i = 0; i < TOPK; i++) { e[i] = expf(tv[i] - mx); se += e[i]; }
        #pragma unroll
        for (int i = 0; i < TOPK; i++) { wgt[i] = e[i] / se; sidx[i] = em[ti[i]]; }
    }
    __syncthreads();

    // weighted gather of raw memory rows
    float4 accv = make_float4(0.f, 0.f, 0.f, 0.f);
    #pragma unroll
    for (int i = 0; i < TOPK; i++) {
        const float4* mr = reinterpret_cast<const float4*>(mem + (size_t)sidx[i] * DIM);
        float4 m = mr[tid];
        float wg = wgt[i];
        accv.x += wg * m.x; accv.y += wg * m.y; accv.z += wg * m.z; accv.w += wg * m.w;
    }
    reinterpret_cast<float4*>(out + (size_t)row * DIM)[tid] = accv;
}

// ---------------- launch ----------------
extern "C" void kernel_launch(void* const* d_in, const int* in_sizes, int n_in,
                              void* d_out, int out_size) {
    const float* x   = (const float*)d_in[0];
    const float* mem = (const float*)d_in[1];
    float* out = (float*)d_out;

    cudaFuncSetAttribute(gemm_topk_kernel,
                         cudaFuncAttributeMaxDynamicSharedMemorySize, SMEM_BYTES);

    prep_mem_kernel<<<C_ROWS, 256>>>(mem);
    prep_x_kernel<<<B_ROWS, 256>>>(x);
    gemm_topk_kernel<<<dim3(B_ROWS / BM, NTILES), 256, SMEM_BYTES>>>();
    rescore_out_kernel<<<B_ROWS, 256>>>(x, mem, out);
}